// round 1
// baseline (speedup 1.0000x reference)
#include <cuda_runtime.h>

// BackEdgeConv2d: out = x * !(5 <= boxcount7x7(x >= 128/255, reflect-pad) <= 19)
// x: [16, 3, 1024, 1024] fp32. One fused pass, HBM-bound.

#define TILE_W 128
#define TILE_H 32
#define KPAD 3
#define PW (TILE_W + 2*KPAD)     // 134 valid padded cols
#define PH (TILE_H + 2*KPAD)     // 38 padded rows
#define PSTRIDE 136              // byte stride, multiple of 4
#define WPR (PSTRIDE/4)          // 34 words per row
#define NTHREADS 256

__global__ __launch_bounds__(NTHREADS)
void backedge_kernel(const float* __restrict__ x, float* __restrict__ out,
                     int H, int W) {
    __shared__ float sx[TILE_H][TILE_W];                 // 16 KB interior x
    __shared__ unsigned char scond[PH][PSTRIDE];         // ~5.2 KB binary map
    __shared__ unsigned char svsum[TILE_H][PSTRIDE];     // ~4.3 KB vertical 7-sums

    const int tid = threadIdx.x;
    const int c0 = blockIdx.x * TILE_W;
    const int r0 = blockIdx.y * TILE_H;
    const int plane = blockIdx.z * H * W;                // 1M * 48 fits in int
    const float* xp = x + plane;
    float* op = out + plane;
    const float T = 128.0f / 255.0f;

    // ---- Phase 1: load padded tile, threshold to cond; keep interior x in smem
    for (int idx = tid; idx < PH * PSTRIDE; idx += NTHREADS) {
        int pr = idx / PSTRIDE;
        int pc = idx - pr * PSTRIDE;
        if (pc >= PW) { scond[pr][pc] = 0; continue; }   // keep pad bytes defined
        int gr = r0 + pr - KPAD;
        int gc = c0 + pc - KPAD;
        gr = gr < 0 ? -gr : (gr >= H ? 2 * H - 2 - gr : gr);   // reflect (no edge dup)
        gc = gc < 0 ? -gc : (gc >= W ? 2 * W - 2 - gc : gc);
        float v = xp[gr * W + gc];
        scond[pr][pc] = (v >= T) ? (unsigned char)1 : (unsigned char)0;
        int ir = pr - KPAD, ic = pc - KPAD;
        if ((unsigned)ir < TILE_H && (unsigned)ic < TILE_W)
            sx[ir][ic] = v;
    }
    __syncthreads();

    // ---- Phase 2: vertical 7-sum, SIMD 4 bytes per uint32 (values <= 7, no carry)
    {
        const unsigned int* cw = (const unsigned int*)&scond[0][0];
        unsigned int* vw = (unsigned int*)&svsum[0][0];
        for (int idx = tid; idx < TILE_H * WPR; idx += NTHREADS) {
            int r = idx / WPR;
            int wc = idx - r * WPR;
            unsigned int s = 0;
            #pragma unroll
            for (int k = 0; k < 7; k++)
                s += cw[(r + k) * WPR + wc];
            vw[r * WPR + wc] = s;
        }
    }
    __syncthreads();

    // ---- Phase 3: horizontal sliding 7-sum over 4 pixels/thread/row, masked store
    const int tx = tid & 31;       // column group (4 px each)
    const int ty = tid >> 5;       // row within 8-row band
    const int cbase = tx * 4;

    #pragma unroll
    for (int rr = 0; rr < TILE_H; rr += 8) {
        const int r = ty + rr;
        const unsigned int* row = (const unsigned int*)&svsum[r][0];
        // bytes cbase .. cbase+9 needed; cbase % 4 == 0 -> 3 words
        unsigned int w0 = row[tx];
        unsigned int w1 = row[tx + 1];
        unsigned int w2 = row[tx + 2];

        int b0 = (w0      ) & 0xFF, b1 = (w0 >>  8) & 0xFF;
        int b2 = (w0 >> 16) & 0xFF, b3 = (w0 >> 24) & 0xFF;
        int b4 = (w1      ) & 0xFF, b5 = (w1 >>  8) & 0xFF;
        int b6 = (w1 >> 16) & 0xFF, b7 = (w1 >> 24) & 0xFF;
        int b8 = (w2      ) & 0xFF, b9 = (w2 >>  8) & 0xFF;

        int h0 = b0 + b1 + b2 + b3 + b4 + b5 + b6;
        int h1 = h0 - b0 + b7;
        int h2 = h1 - b1 + b8;
        int h3 = h2 - b2 + b9;

        float4 xv = *(const float4*)&sx[r][cbase];
        // band: csum >= 24*0.2 (=4.8) && csum <= 24*0.8 (=19.2)  ->  5..19 inclusive
        float4 ov;
        ov.x = (h0 >= 5 && h0 <= 19) ? 0.0f : xv.x;
        ov.y = (h1 >= 5 && h1 <= 19) ? 0.0f : xv.y;
        ov.z = (h2 >= 5 && h2 <= 19) ? 0.0f : xv.z;
        ov.w = (h3 >= 5 && h3 <= 19) ? 0.0f : xv.w;

        *(float4*)&op[(r0 + r) * W + c0 + cbase] = ov;
    }
}

extern "C" void kernel_launch(void* const* d_in, const int* in_sizes, int n_in,
                              void* d_out, int out_size) {
    const float* x = (const float*)d_in[0];
    float* out = (float*)d_out;
    const int H = 1024, W = 1024;
    const int planes = out_size / (H * W);   // B*C = 48
    dim3 grid(W / TILE_W, H / TILE_H, planes);
    backedge_kernel<<<grid, NTHREADS>>>(x, out, H, W);
}

// round 2
// speedup vs baseline: 1.8807x; 1.8807x over previous
#include <cuda_runtime.h>

// BackEdgeConv2d fused: out = x * !(5 <= boxcount7x7(x >= 128/255, reflect) <= 19)
// x: [16,3,1024,1024] fp32. Word-vectorized cond pipeline; target HBM-bound.

#define TILE_W 128
#define TILE_H 32
#define KPAD 3
#define PH (TILE_H + 2*KPAD)        // 38 padded rows
#define WPR 34                      // words per padded row (136 bytes: left pad 4, right pad to mult of 8)
#define W2PR 17                     // uint2 per row
#define NTHREADS 256

__global__ __launch_bounds__(NTHREADS)
void backedge_kernel(const float* __restrict__ x, float* __restrict__ out,
                     int H, int W) {
    // cond byte j of a row maps to global col (c0 - 4 + j). Interior col i -> j = i+4 (word aligned).
    __shared__ unsigned int scond[PH * WPR];        // 5168 B
    __shared__ unsigned int svsum[TILE_H * WPR];    // 4352 B
    __shared__ float4 sxv[TILE_H * (TILE_W / 4)];   // 16384 B

    const int tid = threadIdx.x;
    const int c0 = blockIdx.x * TILE_W;
    const int r0 = blockIdx.y * TILE_H;
    const long long plane = (long long)blockIdx.z * H * W;
    const float* xp = x + plane;
    float* op = out + plane;
    const float T = 128.0f / 255.0f;

    // ---- Phase 1: padded cond map, one uint32 word (4 px) per iteration
    #pragma unroll 1
    for (int wi = tid; wi < PH * WPR; wi += NTHREADS) {
        int pr = wi / WPR;
        int w  = wi - pr * WPR;
        int gr = r0 + pr - KPAD;
        int gc = c0 + (w << 2) - 4;
        float4 v;
        if ((unsigned)gr < (unsigned)H && (unsigned)gc <= (unsigned)(W - 4)) {
            v = *(const float4*)(xp + gr * W + gc);          // aligned, coalesced
        } else {
            int rr = gr < 0 ? -gr : (gr >= H ? 2 * H - 2 - gr : gr);
            const float* rowp = xp + rr * W;
            int g0 = gc, g1 = gc + 1, g2 = gc + 2, g3 = gc + 3;
            g0 = g0 < 0 ? -g0 : (g0 >= W ? 2 * W - 2 - g0 : g0);
            g1 = g1 < 0 ? -g1 : (g1 >= W ? 2 * W - 2 - g1 : g1);
            g2 = g2 < 0 ? -g2 : (g2 >= W ? 2 * W - 2 - g2 : g2);
            g3 = g3 < 0 ? -g3 : (g3 >= W ? 2 * W - 2 - g3 : g3);
            v.x = rowp[g0]; v.y = rowp[g1]; v.z = rowp[g2]; v.w = rowp[g3];
        }
        unsigned int b0 = (v.x >= T) ? 1u : 0u;
        unsigned int b1 = (v.y >= T) ? 1u : 0u;
        unsigned int b2 = (v.z >= T) ? 1u : 0u;
        unsigned int b3 = (v.w >= T) ? 1u : 0u;
        scond[wi] = b0 | (b1 << 8) | (b2 << 16) | (b3 << 24);
        int ir = pr - KPAD, iw = w - 1;                     // interior float4 tile
        if ((unsigned)ir < (unsigned)TILE_H && (unsigned)iw < (unsigned)(TILE_W / 4))
            sxv[ir * (TILE_W / 4) + iw] = v;
    }
    __syncthreads();

    // ---- Phase 2: vertical 7-sum, SIMD bytes, 8 px (uint2) per iteration
    {
        const uint2* c2 = (const uint2*)scond;
        uint2* v2 = (uint2*)svsum;
        #pragma unroll 1
        for (int wi = tid; wi < TILE_H * W2PR; wi += NTHREADS) {
            uint2 s = c2[wi];
            #pragma unroll
            for (int k = 1; k < 7; k++) {
                uint2 a = c2[wi + k * W2PR];
                s.x += a.x; s.y += a.y;
            }
            v2[wi] = s;
        }
    }
    __syncthreads();

    // ---- Phase 3: horizontal sliding 7-sum via dp4a, 4 px/thread/row
    const int tx = tid & 31;        // word group -> cols [4tx, 4tx+3]
    const int ty = tid >> 5;
    {
        #pragma unroll
        for (int rr = 0; rr < TILE_H; rr += 8) {
            const int r = ty + rr;
            const unsigned int* row = &svsum[r * WPR];
            unsigned int w0 = row[tx];
            unsigned int w1 = row[tx + 1];
            unsigned int w2 = row[tx + 2];

            // window bytes a1..a10 of the 12-byte span starting at byte 4*tx
            int h0 = __dp4a(w0, 0x01010100u, 0u);           // a1+a2+a3
            h0 = __dp4a(w1, 0x01010101u, (unsigned)h0);     // + a4..a7
            int a1 = (w0 >> 8)  & 0xFF;
            int a2 = (w0 >> 16) & 0xFF;
            int a3 = (w0 >> 24) & 0xFF;
            int a8 = w2 & 0xFF;
            int a9 = (w2 >> 8)  & 0xFF;
            int a10 = (w2 >> 16) & 0xFF;
            int h1 = h0 - a1 + a8;
            int h2 = h1 - a2 + a9;
            int h3 = h2 - a3 + a10;

            float4 xv = sxv[r * (TILE_W / 4) + tx];
            float4 ov;
            ov.x = ((unsigned)(h0 - 5) <= 14u) ? 0.0f : xv.x;   // band 5..19 inclusive
            ov.y = ((unsigned)(h1 - 5) <= 14u) ? 0.0f : xv.y;
            ov.z = ((unsigned)(h2 - 5) <= 14u) ? 0.0f : xv.z;
            ov.w = ((unsigned)(h3 - 5) <= 14u) ? 0.0f : xv.w;

            *(float4*)&op[(r0 + r) * W + c0 + (tx << 2)] = ov;
        }
    }
}

extern "C" void kernel_launch(void* const* d_in, const int* in_sizes, int n_in,
                              void* d_out, int out_size) {
    const float* x = (const float*)d_in[0];
    float* out = (float*)d_out;
    const int H = 1024, W = 1024;
    const int planes = out_size / (H * W);   // B*C = 48
    dim3 grid(W / TILE_W, H / TILE_H, planes);
    backedge_kernel<<<grid, NTHREADS>>>(x, out, H, W);
}

// round 3
// speedup vs baseline: 2.1471x; 1.1417x over previous
#include <cuda_runtime.h>

// BackEdgeConv2d fused: out = x * !(5 <= boxcount7x7(x >= 128/255, reflect) <= 19)
// x: [16,3,1024,1024] fp32. One pass, word-vectorized; target HBM-bound.

#define TILE_W 128
#define TILE_H 64
#define KPAD 3
#define PH (TILE_H + 2*KPAD)        // 70 padded rows
#define WPR 34                      // 136 cond bytes/row: byte j <-> global col c0-4+j
#define W2PR 17                     // uint2 per row
#define NTHREADS 256

__global__ __launch_bounds__(NTHREADS)
void backedge_kernel(const float* __restrict__ x, float* __restrict__ out,
                     int H, int W) {
    __shared__ __align__(16) unsigned int scond[PH * WPR];      // 9520 B
    __shared__ __align__(16) unsigned int svsum[TILE_H * WPR];  // 8704 B

    const int tid = threadIdx.x;
    const int c0 = blockIdx.x * TILE_W;
    const int r0 = blockIdx.y * TILE_H;
    const long long plane = (long long)blockIdx.z * H * W;
    const float* xp = x + plane;
    float* op = out + plane;
    const float T = 128.0f / 255.0f;

    // ---- Phase 1: padded cond map, one uint32 word (4 px) per iteration
    #pragma unroll 1
    for (int wi = tid; wi < PH * WPR; wi += NTHREADS) {
        int pr = wi / WPR;                    // const divisor -> mul.hi
        int w  = wi - pr * WPR;
        int gr = r0 + pr - KPAD;
        int gc = c0 + (w << 2) - 4;
        float4 v;
        if ((unsigned)gr < (unsigned)H && (unsigned)gc <= (unsigned)(W - 4)) {
            v = *(const float4*)(xp + gr * W + gc);          // aligned, coalesced
        } else {
            int rr = gr < 0 ? -gr : (gr >= H ? 2 * H - 2 - gr : gr);
            const float* rowp = xp + rr * W;
            int g0 = gc, g1 = gc + 1, g2 = gc + 2, g3 = gc + 3;
            g0 = g0 < 0 ? -g0 : (g0 >= W ? 2 * W - 2 - g0 : g0);
            g1 = g1 < 0 ? -g1 : (g1 >= W ? 2 * W - 2 - g1 : g1);
            g2 = g2 < 0 ? -g2 : (g2 >= W ? 2 * W - 2 - g2 : g2);
            g3 = g3 < 0 ? -g3 : (g3 >= W ? 2 * W - 2 - g3 : g3);
            v.x = rowp[g0]; v.y = rowp[g1]; v.z = rowp[g2]; v.w = rowp[g3];
        }
        unsigned int b0 = (v.x >= T) ? 1u : 0u;
        unsigned int b1 = (v.y >= T) ? (1u << 8) : 0u;
        unsigned int b2 = (v.z >= T) ? (1u << 16) : 0u;
        unsigned int b3 = (v.w >= T) ? (1u << 24) : 0u;
        scond[wi] = (b0 | b1) | (b2 | b3);
    }
    __syncthreads();

    // ---- Phase 2: vertical 7-sum, SIMD bytes, 8 px (uint2) per iteration
    {
        const uint2* c2 = (const uint2*)scond;
        uint2* v2 = (uint2*)svsum;
        #pragma unroll 1
        for (int wi = tid; wi < TILE_H * W2PR; wi += NTHREADS) {
            uint2 s = c2[wi];
            #pragma unroll
            for (int k = 1; k < 7; k++) {
                uint2 a = c2[wi + k * W2PR];
                s.x += a.x; s.y += a.y;
            }
            v2[wi] = s;
        }
    }
    __syncthreads();

    // ---- Phase 3: horizontal sliding 7-sum via dp4a, 4 px/thread/row;
    //      x re-read from global (L1/L2-hot from phase 1), streaming store.
    const int tx = tid & 31;        // word group -> cols [4tx .. 4tx+3]
    const int ty = tid >> 5;
    #pragma unroll
    for (int rr = 0; rr < TILE_H; rr += 8) {
        const int r = ty + rr;
        const unsigned int* row = &svsum[r * WPR];
        unsigned int w0 = row[tx];
        unsigned int w1 = row[tx + 1];
        unsigned int w2 = row[tx + 2];

        // window bytes a1..a10 of the 12-byte span starting at byte 4*tx
        int h0 = __dp4a(w0, 0x01010100u, 0u);           // a1+a2+a3
        h0 = __dp4a(w1, 0x01010101u, (unsigned)h0);     // + a4..a7
        int a1  = (w0 >> 8)  & 0xFF;
        int a2  = (w0 >> 16) & 0xFF;
        int a3  = (w0 >> 24) & 0xFF;
        int a8  =  w2        & 0xFF;
        int a9  = (w2 >> 8)  & 0xFF;
        int a10 = (w2 >> 16) & 0xFF;
        int h1 = h0 - a1 + a8;
        int h2 = h1 - a2 + a9;
        int h3 = h2 - a3 + a10;

        const float* gp = xp + (long long)(r0 + r) * W + c0 + (tx << 2);
        float4 xv = *(const float4*)gp;
        float4 ov;
        ov.x = ((unsigned)(h0 - 5) <= 14u) ? 0.0f : xv.x;   // band 5..19 inclusive
        ov.y = ((unsigned)(h1 - 5) <= 14u) ? 0.0f : xv.y;
        ov.z = ((unsigned)(h2 - 5) <= 14u) ? 0.0f : xv.z;
        ov.w = ((unsigned)(h3 - 5) <= 14u) ? 0.0f : xv.w;

        __stcs((float4*)&op[(long long)(r0 + r) * W + c0 + (tx << 2)], ov);
    }
}

extern "C" void kernel_launch(void* const* d_in, const int* in_sizes, int n_in,
                              void* d_out, int out_size) {
    const float* x = (const float*)d_in[0];
    float* out = (float*)d_out;
    const int H = 1024, W = 1024;
    const int planes = out_size / (H * W);   // B*C = 48
    dim3 grid(W / TILE_W, H / TILE_H, planes);
    backedge_kernel<<<grid, NTHREADS>>>(x, out, H, W);
}